// round 15
// baseline (speedup 1.0000x reference)
#include <cuda_runtime.h>
#include <cuda_fp16.h>
#include <math.h>
#include <stdint.h>

#define BB   8
#define CIN  64
#define COUT 64
#define CG   16
#define HH   128
#define WW   128

// weight fragments fp16x2: [p(9)][kt(4)][ng(4)][lane(32)][j(4)]
__device__ uint32_t g_wfrag[9 * 4 * 4 * 32 * 4];

// smem layout (bytes)
#define SOFF_BIAS 0                    // 256
#define SOFF_KERN 256                  // 9*128*2 (half) = 2304
#define SOFF_B    2560                 // 2 x 8192 double buffer
#define SOFF_XH   18944                // [dh(3)][col(130)][c(64 pad 72)] fp16
#define SMEM_TOTAL (18944 + 3 * 130 * 72 * 2)   // 75104

__device__ __forceinline__ uint32_t smem_u32(const void* p) {
    uint32_t a;
    asm("{ .reg .u64 t; cvta.to.shared.u64 t, %1; cvt.u32.u64 %0, t; }"
        : "=r"(a) : "l"(p));
    return a;
}
__device__ __forceinline__ void ldm_x4(uint32_t r[4], uint32_t addr) {
    asm volatile("ldmatrix.sync.aligned.m8n8.x4.shared.b16 {%0,%1,%2,%3}, [%4];"
                 : "=r"(r[0]), "=r"(r[1]), "=r"(r[2]), "=r"(r[3]) : "r"(addr));
}
__device__ __forceinline__ uint32_t hmul2(uint32_t a, uint32_t k) {
    uint32_t d;
    asm("mul.f16x2 %0, %1, %2;" : "=r"(d) : "r"(a), "r"(k));
    return d;
}
#define MMA_F16(d, a, b0, b1)                                                  \
    asm volatile("mma.sync.aligned.m16n8k16.row.col.f32.f16.f16.f32 "          \
                 "{%0,%1,%2,%3}, {%4,%5,%6,%7}, {%8,%9}, {%0,%1,%2,%3};"       \
                 : "+f"((d)[0]), "+f"((d)[1]), "+f"((d)[2]), "+f"((d)[3])      \
                 : "r"((a)[0]), "r"((a)[1]), "r"((a)[2]), "r"((a)[3]),         \
                   "r"(b0), "r"(b1))
#define CP_ASYNC16(dst, src)                                                   \
    asm volatile("cp.async.ca.shared.global [%0], [%1], 16;"                   \
                 :: "r"(dst), "l"(src) : "memory")
#define CP_COMMIT() asm volatile("cp.async.commit_group;" ::: "memory")
#define CP_WAIT_ALL() asm volatile("cp.async.wait_group 0;" ::: "memory")

// issue one tap's B (8192B) into buffer `buf` — 2 x 16B per thread
#define ISSUE_B(p_, buf_) do {                                                 \
    const char* s_ = (const char*)g_wfrag + (size_t)(p_) * 8192;               \
    uint32_t d_ = sb + SOFF_B + (uint32_t)((buf_) * 8192 + tid * 16);          \
    CP_ASYNC16(d_, s_ + tid * 16);                                             \
    CP_ASYNC16(d_ + 4096u, s_ + tid * 16 + 4096);                              \
    CP_COMMIT();                                                               \
} while (0)

// ---------------------------------------------------------------------------
// weight prep: mma B-fragment order, fp16 (unchanged — proven)
// ---------------------------------------------------------------------------
__global__ void weight_split(const float* __restrict__ weight) {
    int i = blockIdx.x * 256 + threadIdx.x;
    if (i >= 9 * 4 * 4 * 32 * 4) return;
    int p    = i >> 11;
    int kt   = (i >> 9) & 3;
    int ng   = (i >> 7) & 3;
    int lane = (i >> 2) & 31;
    int j    = i & 3;
    int o = (ng * 2 + (j >> 1)) * 8 + (lane >> 2);
    int c = kt * 16 + (lane & 3) * 2 + (j & 1) * 8;
    __half h0 = __float2half_rn(weight[((size_t)o * CIN + c) * 9 + p]);
    __half h1 = __float2half_rn(weight[((size_t)o * CIN + c + 1) * 9 + p]);
    g_wfrag[i] = ((uint32_t)__half_as_ushort(h1) << 16) | __half_as_ushort(h0);
}

// ---------------------------------------------------------------------------
// Main: one CTA = ONE output row, 256 threads, 3 CTAs/SM.
// 8 warps: warpM = wid&3 (32-pixel block), warpN = wid>>2 (32 couts).
// B double-buffered in smem via cp.async (one tap ahead); all operands LDS.
// ---------------------------------------------------------------------------
__global__ __launch_bounds__(256, 3)
void pac_mma(const float* __restrict__ x,
             const float* __restrict__ guide,
             const float* __restrict__ bias,
             float* __restrict__ out) {
    extern __shared__ __align__(16) char smem[];
    const uint32_t sb = smem_u32(smem);
    float*           bias_s = (float*)(smem + SOFF_BIAS);
    unsigned short*  kern_s = (unsigned short*)(smem + SOFF_KERN); // [p][pix] half
    __half*          xh_s   = (__half*)(smem + SOFF_XH);

    const int tid   = threadIdx.x;
    const int lane  = tid & 31;
    const int wid   = tid >> 5;
    const int warpM = wid & 3;
    const int warpN = wid >> 2;
    const int h = blockIdx.x;
    const int b = blockIdx.y;

    // ---- kick off B tap-0 copy immediately ----
    ISSUE_B(0, 0);

    // ---- stage x halo fp16, [dh(3)][col(130)][c] stride 72; STS.128 ----
    for (int i = tid; i < 3120; i += 256) {   // 3 dh * 8 c_oct * 130 col
        int col = i % 130;
        int q   = i / 130;
        int c0  = (q & 7) * 8;
        int dh  = q >> 3;
        int gr = h - 1 + dh, gc = col - 1;
        const bool ok = (gr >= 0) && (gr < HH) && (gc >= 0) && (gc < WW);
        const float* xp = x + ((size_t)(b * CIN + c0) * HH + gr) * WW + gc;
        __half hv[8];
#pragma unroll
        for (int j = 0; j < 8; j++) {
            float v = ok ? __ldg(xp + (size_t)j * (HH * WW)) : 0.f;
            hv[j] = __float2half_rn(v);
        }
        *(uint4*)(xh_s + (dh * 130 + col) * 72 + c0) = *(const uint4*)hv;
    }
    if (tid < COUT) bias_s[tid] = bias[tid];

    // ---- gaussian taps from global guide (L2-hot), store half ----
    if (tid < 128) {
        const int pix = tid;
        const float* gb = guide + (size_t)b * CG * HH * WW;
        float gc[CG];
#pragma unroll
        for (int c = 0; c < CG; c++)
            gc[c] = __ldg(&gb[c * HH * WW + h * WW + pix]);
#pragma unroll
        for (int p = 0; p < 9; p++) {
            int gr = h - 1 + p / 3;
            int gw = pix - 1 + p % 3;
            float ss = 0.f;
            if (gr >= 0 && gr < HH && gw >= 0 && gw < WW) {
#pragma unroll
                for (int c = 0; c < CG; c++) {
                    float d = __ldg(&gb[c * HH * WW + gr * WW + gw]) - gc[c];
                    ss = fmaf(d, d, ss);
                }
            } else {
#pragma unroll
                for (int c = 0; c < CG; c++) ss = fmaf(gc[c], gc[c], ss);
            }
            float kv = __expf(-0.5f * ss);
            kern_s[p * 128 + pix] = __half_as_ushort(__float2half_rn(kv));
        }
    }
    __syncthreads();   // x halo + kern ready

    float acc[2][4][4];
#pragma unroll
    for (int i = 0; i < 2; i++)
#pragma unroll
        for (int j = 0; j < 4; j++)
#pragma unroll
            for (int k = 0; k < 4; k++) acc[i][j][k] = 0.f;

    const int pixb = warpM * 32;
    const uint32_t a_base = sb + SOFF_XH +
        (uint32_t)(((pixb + (lane & 15)) * 72 + ((lane >> 4) << 3)) * 2);
    const uint32_t b_lane = sb + SOFF_B + (uint32_t)(warpN * 1024 + lane * 16);
    const int pix0 = pixb + (lane >> 2);

    // ---- mainloop: 9 taps; B double-buffered via cp.async (1 tap ahead) ----
#pragma unroll
    for (int p = 0; p < 9; p++) {
        const int dh = p / 3, dw = p - dh * 3;

        CP_WAIT_ALL();     // tap-p B landed (issued last iteration / prologue)
        __syncthreads();   // visible to all; prev tap's reads done
        if (p < 8) ISSUE_B(p + 1, (p + 1) & 1);   // overlap with compute

        const uint32_t a_tap = a_base + (uint32_t)((dh * 130 + dw) * 144);
        const uint32_t b_tap = b_lane + (uint32_t)((p & 1) * 8192);

        uint32_t kv2[2][2];
        if (p != 4) {                 // center tap: kv == 1 exactly, skip fold
#pragma unroll
            for (int mt = 0; mt < 2; mt++) {
                uint32_t u0 = kern_s[p * 128 + pix0 + mt * 16];
                uint32_t u1 = kern_s[p * 128 + pix0 + mt * 16 + 8];
                kv2[mt][0] = (u0 << 16) | u0;
                kv2[mt][1] = (u1 << 16) | u1;
            }
        }

#pragma unroll
        for (int kt = 0; kt < 4; kt++) {
            uint32_t b0x, b0y, b0z, b0w, b1x, b1y, b1z, b1w;
            asm volatile("ld.shared.v4.u32 {%0,%1,%2,%3}, [%4];"
                         : "=r"(b0x), "=r"(b0y), "=r"(b0z), "=r"(b0w)
                         : "r"(b_tap + (uint32_t)(kt * 2048)));
            asm volatile("ld.shared.v4.u32 {%0,%1,%2,%3}, [%4];"
                         : "=r"(b1x), "=r"(b1y), "=r"(b1z), "=r"(b1w)
                         : "r"(b_tap + (uint32_t)(kt * 2048 + 512)));
#pragma unroll
            for (int mt = 0; mt < 2; mt++) {
                uint32_t A[4];
                ldm_x4(A, a_tap + (uint32_t)(kt * 32 + mt * 2304));
                if (p != 4) {
                    // row map: A[0],A[2] -> pixel g ; A[1],A[3] -> pixel g+8
                    A[0] = hmul2(A[0], kv2[mt][0]);
                    A[2] = hmul2(A[2], kv2[mt][0]);
                    A[1] = hmul2(A[1], kv2[mt][1]);
                    A[3] = hmul2(A[3], kv2[mt][1]);
                }
                MMA_F16(acc[mt][0], A, b0x, b0y);
                MMA_F16(acc[mt][1], A, b0z, b0w);
                MMA_F16(acc[mt][2], A, b1x, b1y);
                MMA_F16(acc[mt][3], A, b1z, b1w);
            }
        }
    }

    // ---- epilogue: bias + relu ----
#pragma unroll
    for (int mt = 0; mt < 2; mt++) {
        const int pix = pix0 + mt * 16;
#pragma unroll
        for (int nt = 0; nt < 4; nt++) {
            int o = (warpN * 4 + nt) * 8 + (lane & 3) * 2;
            float b0 = bias_s[o], b1 = bias_s[o + 1];
            float* op = out + (((size_t)b * COUT + o) * HH + h) * WW;
            op[pix]               = fmaxf(acc[mt][nt][0] + b0, 0.f);
            op[HH * WW + pix]     = fmaxf(acc[mt][nt][1] + b1, 0.f);
            op[pix + 8]           = fmaxf(acc[mt][nt][2] + b0, 0.f);
            op[HH * WW + pix + 8] = fmaxf(acc[mt][nt][3] + b1, 0.f);
        }
    }
}

// ---------------------------------------------------------------------------
extern "C" void kernel_launch(void* const* d_in, const int* in_sizes, int n_in,
                              void* d_out, int out_size) {
    const float* x      = (const float*)d_in[0];   // (8,64,128,128)
    const float* guide  = (const float*)d_in[1];   // (8,16,128,128)
    const float* weight = (const float*)d_in[2];   // (64,64,3,3)
    const float* bias   = (const float*)d_in[3];   // (64,)
    float* out = (float*)d_out;                    // (8,64,128,128)

    (void)in_sizes; (void)n_in; (void)out_size;

    cudaFuncSetAttribute(pac_mma, cudaFuncAttributeMaxDynamicSharedMemorySize,
                         SMEM_TOTAL);

    weight_split<<<(9 * 4 * 4 * 32 * 4 + 255) / 256, 256>>>(weight);

    dim3 grid(HH, BB);
    pac_mma<<<grid, 256, SMEM_TOTAL>>>(x, guide, bias, out);
}

// round 16
// speedup vs baseline: 1.1397x; 1.1397x over previous
#include <cuda_runtime.h>
#include <cuda_fp16.h>
#include <math.h>
#include <stdint.h>

#define BB   8
#define CIN  64
#define COUT 64
#define CG   16
#define HH   128
#define WW   128

// weight fragments fp16x2: [p(9)][kt(4)][ng(4)][lane(32)][j(4)]
__device__ uint32_t g_wfrag[9 * 4 * 4 * 32 * 4];

// smem layout (bytes)
#define SOFF_BIAS 0                    // 256
#define SOFF_KERN 256                  // 9*128*2 (half) = 2304
#define SOFF_XH   2560                 // [dh(3)][col(130)][c(64 pad 72)] fp16
#define SMEM_TOTAL (2560 + 3 * 130 * 72 * 2)   // 58720

__device__ __forceinline__ uint32_t smem_u32(const void* p) {
    uint32_t a;
    asm("{ .reg .u64 t; cvta.to.shared.u64 t, %1; cvt.u32.u64 %0, t; }"
        : "=r"(a) : "l"(p));
    return a;
}
__device__ __forceinline__ void ldm_x4(uint32_t r[4], uint32_t addr) {
    asm volatile("ldmatrix.sync.aligned.m8n8.x4.shared.b16 {%0,%1,%2,%3}, [%4];"
                 : "=r"(r[0]), "=r"(r[1]), "=r"(r[2]), "=r"(r[3]) : "r"(addr));
}
__device__ __forceinline__ uint32_t hmul2(uint32_t a, uint32_t k) {
    uint32_t d;
    asm("mul.f16x2 %0, %1, %2;" : "=r"(d) : "r"(a), "r"(k));
    return d;
}
#define MMA_F16(d, a, b0, b1)                                                  \
    asm volatile("mma.sync.aligned.m16n8k16.row.col.f32.f16.f16.f32 "          \
                 "{%0,%1,%2,%3}, {%4,%5,%6,%7}, {%8,%9}, {%0,%1,%2,%3};"       \
                 : "+f"((d)[0]), "+f"((d)[1]), "+f"((d)[2]), "+f"((d)[3])      \
                 : "r"((a)[0]), "r"((a)[1]), "r"((a)[2]), "r"((a)[3]),         \
                   "r"(b0), "r"(b1))

// ---------------------------------------------------------------------------
// weight prep: mma B-fragment order, fp16 (unchanged — proven)
// ---------------------------------------------------------------------------
__global__ void weight_split(const float* __restrict__ weight) {
    int i = blockIdx.x * 256 + threadIdx.x;
    if (i >= 9 * 4 * 4 * 32 * 4) return;
    int p    = i >> 11;
    int kt   = (i >> 9) & 3;
    int ng   = (i >> 7) & 3;
    int lane = (i >> 2) & 31;
    int j    = i & 3;
    int o = (ng * 2 + (j >> 1)) * 8 + (lane >> 2);
    int c = kt * 16 + (lane & 3) * 2 + (j & 1) * 8;
    __half h0 = __float2half_rn(weight[((size_t)o * CIN + c) * 9 + p]);
    __half h1 = __float2half_rn(weight[((size_t)o * CIN + c + 1) * 9 + p]);
    g_wfrag[i] = ((uint32_t)__half_as_ushort(h1) << 16) | __half_as_ushort(h0);
}

// ---------------------------------------------------------------------------
// Main: one CTA = ONE output row, 256 threads, 3 CTAs/SM.
// Overlapped prologue: threads 0-127 compute gaussian taps, threads 128-255
// stage the x halo concurrently. Mainloop identical to the proven R13 kernel:
// 8 warps, warp tile 32pix x 32cout, kv folded into A, B via LDG.128 from L2.
// ---------------------------------------------------------------------------
__global__ __launch_bounds__(256, 3)
void pac_mma(const float* __restrict__ x,
             const float* __restrict__ guide,
             const float* __restrict__ bias,
             float* __restrict__ out) {
    extern __shared__ __align__(16) char smem[];
    const uint32_t sb = smem_u32(smem);
    float*          bias_s = (float*)(smem + SOFF_BIAS);
    unsigned short* kern_s = (unsigned short*)(smem + SOFF_KERN); // [p][pix] half
    __half*         xh_s   = (__half*)(smem + SOFF_XH);

    const int tid   = threadIdx.x;
    const int lane  = tid & 31;
    const int wid   = tid >> 5;
    const int warpM = wid & 3;
    const int warpN = wid >> 2;
    const int h = blockIdx.x;
    const int b = blockIdx.y;

    if (tid < 128) {
        // ---- gaussian taps from global guide (L2-hot), store half ----
        const int pix = tid;
        const float* gb = guide + (size_t)b * CG * HH * WW;
        float gc[CG];
#pragma unroll
        for (int c = 0; c < CG; c++)
            gc[c] = __ldg(&gb[c * HH * WW + h * WW + pix]);
#pragma unroll
        for (int p = 0; p < 9; p++) {
            int gr = h - 1 + p / 3;
            int gw = pix - 1 + p % 3;
            float ss = 0.f;
            if (gr >= 0 && gr < HH && gw >= 0 && gw < WW) {
#pragma unroll
                for (int c = 0; c < CG; c++) {
                    float d = __ldg(&gb[c * HH * WW + gr * WW + gw]) - gc[c];
                    ss = fmaf(d, d, ss);
                }
            } else {
#pragma unroll
                for (int c = 0; c < CG; c++) ss = fmaf(gc[c], gc[c], ss);
            }
            float kv = __expf(-0.5f * ss);
            kern_s[p * 128 + pix] = __half_as_ushort(__float2half_rn(kv));
        }
        // bias (threads 64-127 idle-cheap)
        if (tid < COUT) bias_s[tid] = bias[tid];
    } else {
        // ---- stage x halo fp16, [dh(3)][col(130)][c] stride 72; STS.128 ----
        for (int i = tid - 128; i < 3120; i += 128) {   // 3 dh * 8 c_oct * 130
            int col = i % 130;
            int q   = i / 130;
            int c0  = (q & 7) * 8;
            int dh  = q >> 3;
            int gr = h - 1 + dh, gc = col - 1;
            const bool ok = (gr >= 0) && (gr < HH) && (gc >= 0) && (gc < WW);
            const float* xp = x + ((size_t)(b * CIN + c0) * HH + gr) * WW + gc;
            __half hv[8];
#pragma unroll
            for (int j = 0; j < 8; j++) {
                float v = ok ? __ldg(xp + (size_t)j * (HH * WW)) : 0.f;
                hv[j] = __float2half_rn(v);
            }
            *(uint4*)(xh_s + (dh * 130 + col) * 72 + c0) = *(const uint4*)hv;
        }
    }
    __syncthreads();

    float acc[2][4][4];
#pragma unroll
    for (int i = 0; i < 2; i++)
#pragma unroll
        for (int j = 0; j < 4; j++)
#pragma unroll
            for (int k = 0; k < 4; k++) acc[i][j][k] = 0.f;

    const int pixb = warpM * 32;
    const uint32_t a_base = sb + SOFF_XH +
        (uint32_t)(((pixb + (lane & 15)) * 72 + ((lane >> 4) << 3)) * 2);
    const uint4* b_base = (const uint4*)g_wfrag + warpN * 64 + lane;
    const int pix0 = pixb + (lane >> 2);

    // ---- mainloop: 9 taps, barrier-free, kv folded into A (R13-proven) ----
#pragma unroll
    for (int p = 0; p < 9; p++) {
        const int dh = p / 3, dw = p - dh * 3;
        const uint32_t a_tap = a_base + (uint32_t)((dh * 130 + dw) * 144);
        const uint4* bt = b_base + (size_t)(p * 4) * 128;

        uint32_t kv2[2][2];
        if (p != 4) {                 // center tap: kv == 1 exactly, skip fold
#pragma unroll
            for (int mt = 0; mt < 2; mt++) {
                uint32_t u0 = kern_s[p * 128 + pix0 + mt * 16];
                uint32_t u1 = kern_s[p * 128 + pix0 + mt * 16 + 8];
                kv2[mt][0] = (u0 << 16) | u0;
                kv2[mt][1] = (u1 << 16) | u1;
            }
        }

#pragma unroll
        for (int kt = 0; kt < 4; kt++) {
            uint4 b0 = __ldg(bt + (size_t)kt * 128);
            uint4 b1 = __ldg(bt + (size_t)kt * 128 + 32);
#pragma unroll
            for (int mt = 0; mt < 2; mt++) {
                uint32_t A[4];
                ldm_x4(A, a_tap + (uint32_t)(kt * 32 + mt * 2304));
                if (p != 4) {
                    // row map: A[0],A[2] -> pixel g ; A[1],A[3] -> pixel g+8
                    A[0] = hmul2(A[0], kv2[mt][0]);
                    A[2] = hmul2(A[2], kv2[mt][0]);
                    A[1] = hmul2(A[1], kv2[mt][1]);
                    A[3] = hmul2(A[3], kv2[mt][1]);
                }
                MMA_F16(acc[mt][0], A, b0.x, b0.y);
                MMA_F16(acc[mt][1], A, b0.z, b0.w);
                MMA_F16(acc[mt][2], A, b1.x, b1.y);
                MMA_F16(acc[mt][3], A, b1.z, b1.w);
            }
        }
    }

    // ---- epilogue: bias + relu ----
#pragma unroll
    for (int mt = 0; mt < 2; mt++) {
        const int pix = pix0 + mt * 16;
#pragma unroll
        for (int nt = 0; nt < 4; nt++) {
            int o = (warpN * 4 + nt) * 8 + (lane & 3) * 2;
            float b0 = bias_s[o], b1 = bias_s[o + 1];
            float* op = out + (((size_t)b * COUT + o) * HH + h) * WW;
            op[pix]               = fmaxf(acc[mt][nt][0] + b0, 0.f);
            op[HH * WW + pix]     = fmaxf(acc[mt][nt][1] + b1, 0.f);
            op[pix + 8]           = fmaxf(acc[mt][nt][2] + b0, 0.f);
            op[HH * WW + pix + 8] = fmaxf(acc[mt][nt][3] + b1, 0.f);
        }
    }
}

// ---------------------------------------------------------------------------
extern "C" void kernel_launch(void* const* d_in, const int* in_sizes, int n_in,
                              void* d_out, int out_size) {
    const float* x      = (const float*)d_in[0];   // (8,64,128,128)
    const float* guide  = (const float*)d_in[1];   // (8,16,128,128)
    const float* weight = (const float*)d_in[2];   // (64,64,3,3)
    const float* bias   = (const float*)d_in[3];   // (64,)
    float* out = (float*)d_out;                    // (8,64,128,128)

    (void)in_sizes; (void)n_in; (void)out_size;

    cudaFuncSetAttribute(pac_mma, cudaFuncAttributeMaxDynamicSharedMemorySize,
                         SMEM_TOTAL);

    weight_split<<<(9 * 4 * 4 * 32 * 4 + 255) / 256, 256>>>(weight);

    dim3 grid(HH, BB);
    pac_mma<<<grid, 256, SMEM_TOTAL>>>(x, guide, bias, out);
}